// round 1
// baseline (speedup 1.0000x reference)
#include <cuda_runtime.h>
#include <math.h>

#define BB 2
#define SS 1024
#define DM 1024
#define NH 16
#define DH 64
#define MROWS (BB*SS)          // 2048
#define MAXN 0.996f            // (1 - 4e-3)/sqrt(c)

// Scratch (static device globals: allowed; no cudaMalloc anywhere)
__device__ float g_qkv[3][MROWS*DM];   // q,k,v (xz in-place transformed)
__device__ float g_aux[3][MROWS*NH];   // per-(row,head): final ||y||^2
__device__ float g_zn[3][DM];
__device__ float g_ch[3][DM];
__device__ float g_sh[3][DM];

// ---------------------------------------------------------------------------
// Kernel 1: column norms of z matrices + cosh/sinh(2r)
// ---------------------------------------------------------------------------
__global__ void colnorm_kernel(const float* __restrict__ qz, const float* __restrict__ kz,
                               const float* __restrict__ vz, const float* __restrict__ qr,
                               const float* __restrict__ kr, const float* __restrict__ vr) {
    int gid = blockIdx.x * blockDim.x + threadIdx.x;   // 0..3*DM-1
    if (gid >= 3 * DM) return;
    int which = gid / DM;
    int col   = gid % DM;
    const float* z = (which == 0) ? qz : (which == 1) ? kz : vz;
    const float* r = (which == 0) ? qr : (which == 1) ? kr : vr;
    float s = 0.f;
    #pragma unroll 4
    for (int i = 0; i < DM; i++) { float v = z[i * DM + col]; s += v * v; }
    g_zn[which][col] = fmaxf(sqrtf(s), 1e-15f);
    float rv = 2.0f * r[col];
    g_ch[which][col] = coshf(rv);
    g_sh[which][col] = sinhf(rv);
}

// ---------------------------------------------------------------------------
// Kernel 2: SGEMM  P = X @ Z   (M=2048, N=1024, K=1024), batched over z via blockIdx.z
// 128x128 tile, BK=16, 256 threads, 8x8 microtile
// ---------------------------------------------------------------------------
#define BM 128
#define BN 128
#define BK 16
__global__ __launch_bounds__(256, 2)
void gemm_kernel(const float* __restrict__ X, const float* __restrict__ qz,
                 const float* __restrict__ kz, const float* __restrict__ vz) {
    int which = blockIdx.z;
    const float* Z = (which == 0) ? qz : (which == 1) ? kz : vz;
    float* Cw = g_qkv[which];

    __shared__ float As[BK][132];   // transposed A tile, padded
    __shared__ float Bs[BK][BN];

    int t  = threadIdx.x;
    int tx = t & 15, ty = t >> 4;
    int m0 = blockIdx.x * BM;
    int n0 = blockIdx.y * BN;

    int lm = t >> 2;            // 0..63
    int lk = (t & 3) * 4;       // 0,4,8,12
    int bk = t >> 5;            // 0..7
    int bn = (t & 31) * 4;

    float acc[8][8] = {};

    for (int k0 = 0; k0 < DM; k0 += BK) {
        #pragma unroll
        for (int i = 0; i < 2; i++) {
            int m = lm + i * 64;
            float4 v = *(const float4*)&X[(m0 + m) * DM + k0 + lk];
            As[lk + 0][m] = v.x; As[lk + 1][m] = v.y;
            As[lk + 2][m] = v.z; As[lk + 3][m] = v.w;
        }
        #pragma unroll
        for (int i = 0; i < 2; i++) {
            int kk = bk + i * 8;
            *(float4*)&Bs[kk][bn] = *(const float4*)&Z[(k0 + kk) * DM + n0 + bn];
        }
        __syncthreads();
        #pragma unroll
        for (int kk = 0; kk < BK; kk++) {
            float a[8], b[8];
            *(float4*)&a[0] = *(float4*)&As[kk][ty * 4];
            *(float4*)&a[4] = *(float4*)&As[kk][ty * 4 + 64];
            *(float4*)&b[0] = *(float4*)&Bs[kk][tx * 4];
            *(float4*)&b[4] = *(float4*)&Bs[kk][tx * 4 + 64];
            #pragma unroll
            for (int r = 0; r < 8; r++)
                #pragma unroll
                for (int c = 0; c < 8; c++) acc[r][c] += a[r] * b[c];
        }
        __syncthreads();
    }
    #pragma unroll
    for (int r = 0; r < 8; r++) {
        int m = m0 + ((r < 4) ? (ty * 4 + r) : (64 + ty * 4 + r - 4));
        *(float4*)&Cw[m * DM + n0 + tx * 4]      = make_float4(acc[r][0], acc[r][1], acc[r][2], acc[r][3]);
        *(float4*)&Cw[m * DM + n0 + 64 + tx * 4] = make_float4(acc[r][4], acc[r][5], acc[r][6], acc[r][7]);
    }
}

// ---------------------------------------------------------------------------
// Kernel 3: Poincare-linear epilogue, in-place on g_qkv[which]; writes g_aux
// one block per (row, which); 256 threads
// ---------------------------------------------------------------------------
__global__ void proj_epilogue(const float* __restrict__ X) {
    int row   = blockIdx.x;       // 0..2047
    int which = blockIdx.y;       // 0..2
    int t = threadIdx.x;

    __shared__ float ys[DM];
    __shared__ float red[256];
    __shared__ float hscale[NH];

    // cx2 = ||x||^2
    float s = 0.f;
    #pragma unroll
    for (int i = t; i < DM; i += 256) { float v = X[row * DM + i]; s += v * v; }
    red[t] = s; __syncthreads();
    for (int off = 128; off > 0; off >>= 1) {
        if (t < off) red[t] += red[t + off];
        __syncthreads();
    }
    float cx2 = red[0];
    float invden = 1.0f / fmaxf(1.0f - cx2, 1e-15f);
    float opc = 1.0f + cx2;

    float* P = g_qkv[which];
    #pragma unroll
    for (int i = t; i < DM; i += 256) {
        float xz  = P[row * DM + i];
        float zn  = g_zn[which][i];
        float xzu = xz / zn;
        float arg = (2.0f * xzu * g_ch[which][i] - opc * g_sh[which][i]) * invden;
        float w   = 2.0f * zn * asinhf(arg);
        ys[i] = sinhf(w);
    }
    __syncthreads();

    // per-head norms + scalar projections
    int warp = t >> 5, lane = t & 31;
    for (int h = warp; h < NH; h += 8) {
        float v0 = ys[h * DH + lane], v1 = ys[h * DH + 32 + lane];
        float sq = v0 * v0 + v1 * v1;
        for (int off = 16; off > 0; off >>= 1) sq += __shfl_xor_sync(0xffffffffu, sq, off);
        if (lane == 0) {
            float n1  = fmaxf(sqrtf(sq), 1e-15f);
            float s1  = (n1 > MAXN) ? (MAXN / n1) : 1.0f;
            float n1c = n1 * s1;
            float f   = 1.0f / (1.0f + sqrtf(1.0f + n1c * n1c));
            float n2  = fmaxf(n1c * f, 1e-15f);
            float s2  = (n2 > MAXN) ? (MAXN / n2) : 1.0f;
            hscale[h] = s1 * f * s2;
            float n3  = n2 * s2;
            g_aux[which][row * NH + h] = n3 * n3;
        }
    }
    __syncthreads();
    #pragma unroll
    for (int i = t; i < DM; i += 256)
        P[row * DM + i] = ys[i] * hscale[i >> 6];
}

// ---------------------------------------------------------------------------
// Kernel 4: flash-style hyperbolic attention + gyromidpoint
// grid (B*H, S/64); 256 threads; 64 queries per block; 4x4 microtile per thread
// softmax normalization cancels between nomin and denom -> no l accumulator.
// ---------------------------------------------------------------------------
#define SM_FLOATS (4 * 4096 + 4 * 64)
__global__ __launch_bounds__(256, 3)
void attn_kernel(const float* __restrict__ mask, float* __restrict__ out) {
    extern __shared__ float sm[];
    float (*qsT)[64] = (float(*)[64])(sm);            // [dh][i]
    float (*ksT)[64] = (float(*)[64])(sm + 4096);     // [dh][j]
    float (*gvs)[64] = (float(*)[64])(sm + 8192);     // [j][dh]  gamma*v
    float (*ps)[64]  = (float(*)[64])(sm + 12288);    // [i][j]   exp weights
    float* q2s  = sm + 16384;
    float* k2s  = q2s + 64;
    float* gm1s = k2s + 64;
    float* msks = gm1s + 64;

    int bh = blockIdx.x;          // 0..31
    int qt = blockIdx.y;          // 0..15
    int b = bh >> 4, h = bh & 15;
    int t = threadIdx.x, tx = t & 15, ty = t >> 4;

    const float* Q = g_qkv[0];
    const float* K = g_qkv[1];
    const float* V = g_qkv[2];
    int qi0 = qt * 64;

    // load q tile (transposed) + q2
    {
        int i  = t >> 2;
        int d4 = (t & 3) * 4;
        int base = (b * SS + qi0 + i) * DM + h * DH;
        #pragma unroll
        for (int jj = 0; jj < 4; jj++) {
            int dh = d4 + jj * 16;
            float4 v = *(const float4*)&Q[base + dh];
            qsT[dh + 0][i] = v.x; qsT[dh + 1][i] = v.y;
            qsT[dh + 2][i] = v.z; qsT[dh + 3][i] = v.w;
        }
        if (t < 64) q2s[t] = g_aux[0][(b * SS + qi0 + t) * NH + h];
    }
    __syncthreads();

    float acc[4][4] = {};
    float accd[4]   = {};
    float m[4] = {-1e30f, -1e30f, -1e30f, -1e30f};

    for (int kt = 0; kt < SS / 64; kt++) {
        int kj0 = kt * 64;
        {
            int j  = t >> 2;
            int d4 = (t & 3) * 4;
            int kb = (b * SS + kj0 + j) * DM + h * DH;
            float v2    = g_aux[2][(b * SS + kj0 + j) * NH + h];
            float gamma = 2.0f / fmaxf(1.0f - v2, 1e-15f);
            #pragma unroll
            for (int jj = 0; jj < 4; jj++) {
                int dh = d4 + jj * 16;
                float4 kv = *(const float4*)&K[kb + dh];
                ksT[dh + 0][j] = kv.x; ksT[dh + 1][j] = kv.y;
                ksT[dh + 2][j] = kv.z; ksT[dh + 3][j] = kv.w;
                float4 vv = *(const float4*)&V[kb + dh];
                *(float4*)&gvs[j][dh] = make_float4(vv.x * gamma, vv.y * gamma,
                                                    vv.z * gamma, vv.w * gamma);
            }
            if (t < 64) {
                k2s[t]  = g_aux[1][(b * SS + kj0 + t) * NH + h];
                float w2 = g_aux[2][(b * SS + kj0 + t) * NH + h];
                gm1s[t] = 2.0f / fmaxf(1.0f - w2, 1e-15f) - 1.0f;
                msks[t] = mask[b * SS + kj0 + t];
            }
        }
        __syncthreads();

        // QK^T 64x64 tile
        float qk[4][4] = {};
        #pragma unroll 8
        for (int kk = 0; kk < 64; kk++) {
            float a[4], bb[4];
            *(float4*)a  = *(float4*)&qsT[kk][ty * 4];
            *(float4*)bb = *(float4*)&ksT[kk][tx * 4];
            #pragma unroll
            for (int r = 0; r < 4; r++)
                #pragma unroll
                for (int c = 0; c < 4; c++) qk[r][c] += a[r] * bb[c];
        }

        // scores = -arccosh(1 + 2*num/den) + mask; online max/rescale
        #pragma unroll
        for (int r = 0; r < 4; r++) {
            float q2 = q2s[ty * 4 + r];
            float oq = 1.0f - q2;
            float tmax = -1e30f;
            #pragma unroll
            for (int c = 0; c < 4; c++) {
                float k2  = k2s[tx * 4 + c];
                float num = fmaxf(q2 - 2.0f * qk[r][c] + k2, 1e-15f);
                float den = fmaxf(oq * (1.0f - k2), 1e-15f);
                float tt  = 2.0f * num / den;
                float dist = log1pf(tt + sqrtf(tt * (tt + 2.0f)));
                float sc   = -dist + msks[tx * 4 + c];
                qk[r][c] = sc;
                tmax = fmaxf(tmax, sc);
            }
            for (int off = 8; off > 0; off >>= 1)
                tmax = fmaxf(tmax, __shfl_xor_sync(0xffffffffu, tmax, off, 16));
            float mn = fmaxf(m[r], tmax);
            float scale = __expf(m[r] - mn);
            m[r] = mn;
            accd[r] *= scale;
            #pragma unroll
            for (int c = 0; c < 4; c++) acc[r][c] *= scale;
            float p0 = __expf(qk[r][0] - mn), p1 = __expf(qk[r][1] - mn);
            float p2 = __expf(qk[r][2] - mn), p3 = __expf(qk[r][3] - mn);
            accd[r] += p0 * gm1s[tx * 4 + 0] + p1 * gm1s[tx * 4 + 1]
                     + p2 * gm1s[tx * 4 + 2] + p3 * gm1s[tx * 4 + 3];
            *(float4*)&ps[ty * 4 + r][tx * 4] = make_float4(p0, p1, p2, p3);
        }
        __syncthreads();

        // acc += P @ (gamma*V)
        #pragma unroll 8
        for (int jj = 0; jj < 64; jj++) {
            float bb[4];
            *(float4*)bb = *(float4*)&gvs[jj][tx * 4];
            float a0 = ps[ty * 4 + 0][jj], a1 = ps[ty * 4 + 1][jj];
            float a2 = ps[ty * 4 + 2][jj], a3 = ps[ty * 4 + 3][jj];
            #pragma unroll
            for (int c = 0; c < 4; c++) {
                acc[0][c] += a0 * bb[c];
                acc[1][c] += a1 * bb[c];
                acc[2][c] += a2 * bb[c];
                acc[3][c] += a3 * bb[c];
            }
        }
        __syncthreads();
    }

    // finalize: gyromidpoint + project, write out [B,S,H*DH]
    #pragma unroll
    for (int r = 0; r < 4; r++) {
        float d = accd[r];
        for (int off = 8; off > 0; off >>= 1) d += __shfl_xor_sync(0xffffffffu, d, off, 16);
        float invd = 1.0f / fmaxf(d, 1e-10f);
        float tm[4];
        float sq = 0.f;
        #pragma unroll
        for (int c = 0; c < 4; c++) { tm[c] = acc[r][c] * invd; sq += tm[c] * tm[c]; }
        for (int off = 8; off > 0; off >>= 1) sq += __shfl_xor_sync(0xffffffffu, sq, off, 16);
        float f = 1.0f / (1.0f + sqrtf(fmaxf(1.0f - sq, 1e-15f)));
        float n = fmaxf(sqrtf(sq) * f, 1e-15f);
        float s2 = (n > MAXN) ? (MAXN / n) : 1.0f;
        float g = f * s2;
        int qi = qi0 + ty * 4 + r;
        *(float4*)&out[(b * SS + qi) * DM + h * DH + tx * 4] =
            make_float4(tm[0] * g, tm[1] * g, tm[2] * g, tm[3] * g);
    }
}

// ---------------------------------------------------------------------------
extern "C" void kernel_launch(void* const* d_in, const int* in_sizes, int n_in,
                              void* d_out, int out_size) {
    const float* hidden = (const float*)d_in[0];
    const float* amask  = (const float*)d_in[1];
    const float* qz = (const float*)d_in[2];
    const float* qr = (const float*)d_in[3];
    const float* kz = (const float*)d_in[4];
    const float* kr = (const float*)d_in[5];
    const float* vz = (const float*)d_in[6];
    const float* vr = (const float*)d_in[7];
    float* out = (float*)d_out;

    static bool attr_done = false;
    if (!attr_done) {
        cudaFuncSetAttribute(attn_kernel, cudaFuncAttributeMaxDynamicSharedMemorySize,
                             SM_FLOATS * sizeof(float));
        attr_done = true;
    }

    colnorm_kernel<<<(3 * DM + 255) / 256, 256>>>(qz, kz, vz, qr, kr, vr);
    gemm_kernel<<<dim3(MROWS / BM, DM / BN, 3), 256>>>(hidden, qz, kz, vz);
    proj_epilogue<<<dim3(MROWS, 3), 256>>>(hidden);
    attn_kernel<<<dim3(BB * NH, SS / 64), 256, SM_FLOATS * sizeof(float)>>>(amask, out);
}

// round 2
// speedup vs baseline: 1.5678x; 1.5678x over previous
#include <cuda_runtime.h>
#include <math.h>

#define BB 2
#define SS 1024
#define DM 1024
#define NH 16
#define DH 64
#define MROWS (BB*SS)
#define MAXN 0.996f

// scratch
__device__ float g_qkv[3][MROWS*DM];
__device__ float g_aux[3][MROWS*NH];   // per-(row,head) final ||y||^2
__device__ float g_cA[3][DM];          // 2*cosh(2r)/zn
__device__ float g_zn2[3][DM];         // 2*zn
__device__ float g_shv[3][DM];         // sinh(2r)
__device__ float g_cx2[MROWS];         // ||x||^2 per row

__device__ __forceinline__ unsigned f2tf32(float x) {
    unsigned r; asm("cvt.rna.tf32.f32 %0, %1;" : "=r"(r) : "f"(x)); return r;
}
__device__ __forceinline__ void mma8(float* d, const unsigned* a, const unsigned* b) {
    asm volatile("mma.sync.aligned.m16n8k8.row.col.f32.tf32.tf32.f32 "
        "{%0,%1,%2,%3}, {%4,%5,%6,%7}, {%8,%9}, {%0,%1,%2,%3};"
        : "+f"(d[0]), "+f"(d[1]), "+f"(d[2]), "+f"(d[3])
        : "r"(a[0]), "r"(a[1]), "r"(a[2]), "r"(a[3]), "r"(b[0]), "r"(b[1]));
}

// ---------------------------------------------------------------------------
// Kernel 1: z column norms (+cosh/sinh terms) and x row norms
// ---------------------------------------------------------------------------
__global__ void norms_kernel(const float* __restrict__ X,
                             const float* __restrict__ qz, const float* __restrict__ kz,
                             const float* __restrict__ vz, const float* __restrict__ qr,
                             const float* __restrict__ kr, const float* __restrict__ vr) {
    int blk = blockIdx.x, t = threadIdx.x;
    if (blk < 12) {
        int gid = blk * 256 + t;
        int which = gid >> 10, col = gid & 1023;
        const float* z = (which == 0) ? qz : (which == 1) ? kz : vz;
        const float* r = (which == 0) ? qr : (which == 1) ? kr : vr;
        float s = 0.f;
        #pragma unroll 4
        for (int i = 0; i < DM; i++) { float v = z[i * DM + col]; s += v * v; }
        float zn = fmaxf(sqrtf(s), 1e-15f);
        float rv = 2.0f * r[col];
        g_cA[which][col]  = 2.0f * coshf(rv) / zn;
        g_zn2[which][col] = 2.0f * zn;
        g_shv[which][col] = sinhf(rv);
    } else {
        int w = (blk - 12) * 8 + (t >> 5), lane = t & 31;
        #pragma unroll
        for (int i = 0; i < 4; i++) {
            int row = w * 4 + i;
            float s = 0.f;
            #pragma unroll 8
            for (int j = 0; j < 32; j++) { float v = X[row * DM + j * 32 + lane]; s += v * v; }
            #pragma unroll
            for (int off = 16; off > 0; off >>= 1) s += __shfl_xor_sync(0xffffffffu, s, off);
            if (lane == 0) g_cx2[row] = s;
        }
    }
}

// ---------------------------------------------------------------------------
// Kernel 2: tf32 tensor-core GEMM (M=2048,N=1024,K=1024, 3 batches) with the
// Poincare-linear epilogue fused (warp tile 32x64 = exactly one head slice).
// block 128x128, BK=32, 8 warps (4x2), warp tile 32x64 (2 m-tiles, 8 n-tiles)
// ---------------------------------------------------------------------------
__global__ __launch_bounds__(256, 2)
void gemm_proj_kernel(const float* __restrict__ X, const float* __restrict__ qz,
                      const float* __restrict__ kz, const float* __restrict__ vz) {
    int which = blockIdx.z;
    const float* Z = (which == 0) ? qz : (which == 1) ? kz : vz;
    float* Cw = g_qkv[which];

    __shared__ unsigned As[128][36];   // [m][k], stride 36 (=4 mod 32): frag reads conflict-free
    __shared__ unsigned Bs[32][136];   // [k][n], stride 136 (=8 mod 32): frag reads conflict-free

    int t = threadIdx.x;
    int wid = t >> 5, lane = t & 31;
    int L2 = lane >> 2, L0 = lane & 3;
    int wm = wid >> 1, wn = wid & 1;
    int m0 = blockIdx.x * 128, n0 = blockIdx.y * 128;

    float acc[2][8][4] = {};

    for (int k0 = 0; k0 < DM; k0 += 32) {
        #pragma unroll
        for (int j = 0; j < 4; j++) {       // A: 128x32
            int idx = t + j * 256;
            int m = idx >> 3, kc = (idx & 7) * 4;
            float4 v = *(const float4*)&X[(m0 + m) * DM + k0 + kc];
            *(uint4*)&As[m][kc] = make_uint4(f2tf32(v.x), f2tf32(v.y), f2tf32(v.z), f2tf32(v.w));
        }
        #pragma unroll
        for (int j = 0; j < 4; j++) {       // B: 32x128 (no transpose)
            int idx = t + j * 256;
            int kk = idx >> 5, nn = (idx & 31) * 4;
            float4 v = *(const float4*)&Z[(k0 + kk) * DM + n0 + nn];
            *(uint4*)&Bs[kk][nn] = make_uint4(f2tf32(v.x), f2tf32(v.y), f2tf32(v.z), f2tf32(v.w));
        }
        __syncthreads();
        #pragma unroll
        for (int k8 = 0; k8 < 4; k8++) {
            int kb = k8 * 8 + L0;
            unsigned a[2][4];
            #pragma unroll
            for (int mt = 0; mt < 2; mt++) {
                int r = wm * 32 + mt * 16 + L2;
                a[mt][0] = As[r][kb];     a[mt][1] = As[r + 8][kb];
                a[mt][2] = As[r][kb + 4]; a[mt][3] = As[r + 8][kb + 4];
            }
            #pragma unroll
            for (int nt = 0; nt < 8; nt++) {
                int c = wn * 64 + nt * 8 + L2;
                unsigned b[2] = { Bs[kb][c], Bs[kb + 4][c] };
                mma8(acc[0][nt], a[0], b);
                mma8(acc[1][nt], a[1], b);
            }
        }
        __syncthreads();
    }

    // ---- fused Poincare epilogue ----
    float* scA  = (float*)As;          // 128 cols of this block
    float* szn2 = scA + 128;
    float* ssh  = szn2 + 128;
    float* scx  = ssh + 128;
    if (t < 128) {
        scA[t]  = g_cA[which][n0 + t];
        szn2[t] = g_zn2[which][n0 + t];
        ssh[t]  = g_shv[which][n0 + t];
        scx[t]  = g_cx2[m0 + t];
    }
    __syncthreads();

    int head = (n0 >> 6) + wn;         // each warp covers exactly one head's 64 cols
    #pragma unroll
    for (int mt = 0; mt < 2; mt++) {
        #pragma unroll
        for (int hh = 0; hh < 2; hh++) {
            int rloc = wm * 32 + mt * 16 + hh * 8 + L2;
            float cx2 = scx[rloc];
            float invden = 1.0f / fmaxf(1.0f - cx2, 1e-15f);
            float opc = 1.0f + cx2;
            float sq = 0.f;
            #pragma unroll
            for (int nt = 0; nt < 8; nt++) {
                int cl = wn * 64 + nt * 8 + 2 * L0;
                float xz0 = acc[mt][nt][hh * 2 + 0];
                float xz1 = acc[mt][nt][hh * 2 + 1];
                float y0 = sinhf(szn2[cl]     * asinhf((xz0 * scA[cl]     - opc * ssh[cl])     * invden));
                float y1 = sinhf(szn2[cl + 1] * asinhf((xz1 * scA[cl + 1] - opc * ssh[cl + 1]) * invden));
                acc[mt][nt][hh * 2 + 0] = y0;
                acc[mt][nt][hh * 2 + 1] = y1;
                sq += y0 * y0 + y1 * y1;
            }
            sq += __shfl_xor_sync(0xffffffffu, sq, 1);
            sq += __shfl_xor_sync(0xffffffffu, sq, 2);
            float n1  = fmaxf(sqrtf(sq), 1e-15f);
            float s1  = (n1 > MAXN) ? (MAXN / n1) : 1.0f;
            float n1c = n1 * s1;
            float f   = 1.0f / (1.0f + sqrtf(1.0f + n1c * n1c));
            float n2  = fmaxf(n1c * f, 1e-15f);
            float s2v = (n2 > MAXN) ? (MAXN / n2) : 1.0f;
            float hs  = s1 * f * s2v;
            float n3  = n2 * s2v;
            int grow = m0 + rloc;
            if (L0 == 0) g_aux[which][grow * NH + head] = n3 * n3;
            #pragma unroll
            for (int nt = 0; nt < 8; nt++) {
                int cl = wn * 64 + nt * 8 + 2 * L0;
                *(float2*)&Cw[grow * DM + n0 + cl] =
                    make_float2(acc[mt][nt][hh * 2] * hs, acc[mt][nt][hh * 2 + 1] * hs);
            }
        }
    }
}

// ---------------------------------------------------------------------------
// Kernel 3: flash-style hyperbolic attention, tensor-core QK^T and P*(gamma V).
// 128 queries/block, 8 warps (16 rows each), 64-key tiles. smem ~106KB, 2/SM.
// ---------------------------------------------------------------------------
#define ATT_SMEM_WORDS (128*68 + 64*68 + 128*68 + 64*72 + 128 + 64*3)
__global__ __launch_bounds__(256, 2)
void attn_kernel(const float* __restrict__ mask, float* __restrict__ out) {
    extern __shared__ unsigned smu[];
    unsigned (*qsm)[68] = (unsigned(*)[68])smu;                 // [i][d]  tf32 Q
    unsigned (*ksm)[68] = (unsigned(*)[68])(smu + 128*68);      // [j][d]  tf32 K
    unsigned (*ps )[68] = (unsigned(*)[68])(smu + 192*68);      // [i][j]  tf32 P
    unsigned (*vsm)[72] = (unsigned(*)[72])(smu + 320*68);      // [j][d]  tf32 gamma*V (stride 72 = 8 mod 32)
    float* q2s  = (float*)(smu + 320*68 + 64*72);
    float* k2s  = q2s + 128;
    float* gm1s = k2s + 64;
    float* msks = gm1s + 64;

    int bh = blockIdx.x, qt = blockIdx.y;
    int b = bh >> 4, h = bh & 15;
    int t = threadIdx.x, wid = t >> 5, lane = t & 31;
    int L2 = lane >> 2, L0 = lane & 3;
    int qi0 = qt * 128;

    const float* Q = g_qkv[0];
    const float* K = g_qkv[1];
    const float* V = g_qkv[2];

    #pragma unroll
    for (int j = 0; j < 8; j++) {          // Q tile 128x64
        int idx = t + j * 256;
        int row = idx >> 4, c4 = (idx & 15) * 4;
        float4 v = *(const float4*)&Q[(b * SS + qi0 + row) * DM + h * DH + c4];
        *(uint4*)&qsm[row][c4] = make_uint4(f2tf32(v.x), f2tf32(v.y), f2tf32(v.z), f2tf32(v.w));
    }
    if (t < 128) q2s[t] = g_aux[0][(b * SS + qi0 + t) * NH + h];
    __syncthreads();

    int rA = wid * 16 + L2;
    float q2_0 = q2s[rA], q2_1 = q2s[rA + 8];
    float oq0 = 1.0f - q2_0, oq1 = 1.0f - q2_1;

    float o[8][4] = {};
    float accd0 = 0.f, accd1 = 0.f;
    float m0r = -1e30f, m1r = -1e30f;

    for (int kt = 0; kt < SS / 64; kt++) {
        int kj0 = kt * 64;
        #pragma unroll
        for (int j = 0; j < 4; j++) {      // K/V tiles 64x64
            int idx = t + j * 256;
            int row = idx >> 4, c4 = (idx & 15) * 4;
            int gr = b * SS + kj0 + row;
            float4 kv = *(const float4*)&K[gr * DM + h * DH + c4];
            *(uint4*)&ksm[row][c4] = make_uint4(f2tf32(kv.x), f2tf32(kv.y), f2tf32(kv.z), f2tf32(kv.w));
            float v2 = g_aux[2][gr * NH + h];
            float gam = 2.0f / fmaxf(1.0f - v2, 1e-15f);
            float4 vv = *(const float4*)&V[gr * DM + h * DH + c4];
            *(uint4*)&vsm[row][c4] = make_uint4(f2tf32(vv.x * gam), f2tf32(vv.y * gam),
                                                f2tf32(vv.z * gam), f2tf32(vv.w * gam));
        }
        if (t < 64) {
            int gr = b * SS + kj0 + t;
            k2s[t] = g_aux[1][gr * NH + h];
            float v2 = g_aux[2][gr * NH + h];
            gm1s[t] = 2.0f / fmaxf(1.0f - v2, 1e-15f) - 1.0f;
            msks[t] = mask[b * SS + kj0 + t];
        }
        __syncthreads();

        // --- QK^T ---
        float s[8][4] = {};
        #pragma unroll
        for (int k8 = 0; k8 < 8; k8++) {
            int kb = k8 * 8 + L0;
            unsigned a[4] = { qsm[rA][kb], qsm[rA + 8][kb], qsm[rA][kb + 4], qsm[rA + 8][kb + 4] };
            #pragma unroll
            for (int nt = 0; nt < 8; nt++) {
                int c = nt * 8 + L2;
                unsigned bb[2] = { ksm[c][kb], ksm[c][kb + 4] };
                mma8(s[nt], a, bb);
            }
        }

        // --- score transform + online softmax (normalizer cancels) ---
        float pm0 = -1e30f, pm1 = -1e30f;
        #pragma unroll
        for (int nt = 0; nt < 8; nt++) {
            int j0 = nt * 8 + 2 * L0;
            float k20 = k2s[j0], k21 = k2s[j0 + 1];
            float mk0 = msks[j0], mk1 = msks[j0 + 1];
            #pragma unroll
            for (int e = 0; e < 4; e++) {
                float q2v = (e < 2) ? q2_0 : q2_1;
                float oqv = (e < 2) ? oq0 : oq1;
                float k2v = (e & 1) ? k21 : k20;
                float mkv = (e & 1) ? mk1 : mk0;
                float num = fmaxf(q2v - 2.0f * s[nt][e] + k2v, 1e-15f);
                float den = fmaxf(oqv * (1.0f - k2v), 1e-15f);
                float tt  = 2.0f * __fdividef(num, den);
                float dist = __logf(1.0f + tt + sqrtf(tt * (tt + 2.0f)));
                s[nt][e] = -dist + mkv;
            }
            pm0 = fmaxf(pm0, fmaxf(s[nt][0], s[nt][1]));
            pm1 = fmaxf(pm1, fmaxf(s[nt][2], s[nt][3]));
        }
        pm0 = fmaxf(pm0, __shfl_xor_sync(0xffffffffu, pm0, 1));
        pm0 = fmaxf(pm0, __shfl_xor_sync(0xffffffffu, pm0, 2));
        pm1 = fmaxf(pm1, __shfl_xor_sync(0xffffffffu, pm1, 1));
        pm1 = fmaxf(pm1, __shfl_xor_sync(0xffffffffu, pm1, 2));
        float mn0 = fmaxf(m0r, pm0), mn1 = fmaxf(m1r, pm1);
        float sc0 = __expf(m0r - mn0), sc1 = __expf(m1r - mn1);
        m0r = mn0; m1r = mn1;
        accd0 *= sc0; accd1 *= sc1;
        #pragma unroll
        for (int nt = 0; nt < 8; nt++) {
            o[nt][0] *= sc0; o[nt][1] *= sc0;
            o[nt][2] *= sc1; o[nt][3] *= sc1;
        }
        #pragma unroll
        for (int nt = 0; nt < 8; nt++) {
            int j0 = nt * 8 + 2 * L0;
            float p00 = __expf(s[nt][0] - mn0), p01 = __expf(s[nt][1] - mn0);
            float p10 = __expf(s[nt][2] - mn1), p11 = __expf(s[nt][3] - mn1);
            float g0 = gm1s[j0], g1 = gm1s[j0 + 1];
            accd0 += p00 * g0 + p01 * g1;
            accd1 += p10 * g0 + p11 * g1;
            ps[rA][j0]     = f2tf32(p00); ps[rA][j0 + 1]     = f2tf32(p01);
            ps[rA + 8][j0] = f2tf32(p10); ps[rA + 8][j0 + 1] = f2tf32(p11);
        }
        __syncwarp();

        // --- P @ (gamma V) ---
        #pragma unroll
        for (int k8 = 0; k8 < 8; k8++) {
            int kb = k8 * 8 + L0;
            unsigned a[4] = { ps[rA][kb], ps[rA + 8][kb], ps[rA][kb + 4], ps[rA + 8][kb + 4] };
            #pragma unroll
            for (int nt = 0; nt < 8; nt++) {
                int d = nt * 8 + L2;
                unsigned bb[2] = { vsm[kb][d], vsm[kb + 4][d] };
                mma8(o[nt], a, bb);
            }
        }
        __syncthreads();
    }

    // --- finalize: gyromidpoint + project ---
    accd0 += __shfl_xor_sync(0xffffffffu, accd0, 1);
    accd0 += __shfl_xor_sync(0xffffffffu, accd0, 2);
    accd1 += __shfl_xor_sync(0xffffffffu, accd1, 1);
    accd1 += __shfl_xor_sync(0xffffffffu, accd1, 2);
    #pragma unroll
    for (int rh = 0; rh < 2; rh++) {
        float accd = rh ? accd1 : accd0;
        float invd = 1.0f / fmaxf(accd, 1e-10f);
        float tm[8][2];
        float sq = 0.f;
        #pragma unroll
        for (int nt = 0; nt < 8; nt++) {
            tm[nt][0] = o[nt][rh * 2 + 0] * invd;
            tm[nt][1] = o[nt][rh * 2 + 1] * invd;
            sq += tm[nt][0] * tm[nt][0] + tm[nt][1] * tm[nt][1];
        }
        sq += __shfl_xor_sync(0xffffffffu, sq, 1);
        sq += __shfl_xor_sync(0xffffffffu, sq, 2);
        float f = 1.0f / (1.0f + sqrtf(fmaxf(1.0f - sq, 1e-15f)));
        float n = fmaxf(sqrtf(sq) * f, 1e-15f);
        float s2 = (n > MAXN) ? (MAXN / n) : 1.0f;
        float g = f * s2;
        int qrow = qi0 + rA + rh * 8;
        #pragma unroll
        for (int nt = 0; nt < 8; nt++) {
            *(float2*)&out[(b * SS + qrow) * DM + h * DH + nt * 8 + 2 * L0] =
                make_float2(tm[nt][0] * g, tm[nt][1] * g);
        }
    }
}

// ---------------------------------------------------------------------------
extern "C" void kernel_launch(void* const* d_in, const int* in_sizes, int n_in,
                              void* d_out, int out_size) {
    const float* hidden = (const float*)d_in[0];
    const float* amask  = (const float*)d_in[1];
    const float* qz = (const float*)d_in[2];
    const float* qr = (const float*)d_in[3];
    const float* kz = (const float*)d_in[4];
    const float* kr = (const float*)d_in[5];
    const float* vz = (const float*)d_in[6];
    const float* vr = (const float*)d_in[7];
    float* out = (float*)d_out;

    static bool attr_done = false;
    if (!attr_done) {
        cudaFuncSetAttribute(attn_kernel, cudaFuncAttributeMaxDynamicSharedMemorySize,
                             ATT_SMEM_WORDS * 4);
        attr_done = true;
    }

    norms_kernel<<<76, 256>>>(hidden, qz, kz, vz, qr, kr, vr);
    gemm_proj_kernel<<<dim3(MROWS / 128, DM / 128, 3), 256>>>(hidden, qz, kz, vz);
    attn_kernel<<<dim3(BB * NH, SS / 128), 256, ATT_SMEM_WORDS * 4>>>(amask, out);
}

// round 4
// speedup vs baseline: 3.3315x; 2.1249x over previous
#include <cuda_runtime.h>
#include <math.h>

#define BB 2
#define SS 1024
#define DM 1024
#define NH 16
#define DH 64
#define MROWS (BB*SS)
#define MAXN 0.996f

__device__ float g_qkv[3][MROWS*DM];
__device__ float g_aux[3][MROWS*NH];   // per-(row,head) final ||y||^2

__device__ __forceinline__ unsigned f2tf32(float x) {
    unsigned r; asm("cvt.rna.tf32.f32 %0, %1;" : "=r"(r) : "f"(x)); return r;
}
__device__ __forceinline__ void mma8(float* d, const unsigned* a, const unsigned* b) {
    asm volatile("mma.sync.aligned.m16n8k8.row.col.f32.tf32.tf32.f32 "
        "{%0,%1,%2,%3}, {%4,%5,%6,%7}, {%8,%9}, {%0,%1,%2,%3};"
        : "+f"(d[0]), "+f"(d[1]), "+f"(d[2]), "+f"(d[3])
        : "r"(a[0]), "r"(a[1]), "r"(a[2]), "r"(a[3]), "r"(b[0]), "r"(b[1]));
}
__device__ __forceinline__ float fsqrt_a(float x){float r;asm("sqrt.approx.f32 %0,%1;":"=f"(r):"f"(x));return r;}
__device__ __forceinline__ float frcp_a (float x){float r;asm("rcp.approx.f32 %0,%1;" :"=f"(r):"f"(x));return r;}
__device__ __forceinline__ float flg2_a (float x){float r;asm("lg2.approx.f32 %0,%1;" :"=f"(r):"f"(x));return r;}
__device__ __forceinline__ float fex2_a (float x){float r;asm("ex2.approx.f32 %0,%1;" :"=f"(r):"f"(x));return r;}

// ---------------------------------------------------------------------------
// Kernel 1: tf32 GEMM (M=2048,N=1024,K=1024, 3 batches) with fused row/col
// norm reductions and the full Poincare-linear epilogue.
// block 128x128, BK=32, 8 warps (4x2), warp tile 32x64 (one head wide)
// ---------------------------------------------------------------------------
__global__ __launch_bounds__(256, 2)
void gemm_proj_kernel(const float* __restrict__ X, const float* __restrict__ qz,
                      const float* __restrict__ kz, const float* __restrict__ vz,
                      const float* __restrict__ qr, const float* __restrict__ kr,
                      const float* __restrict__ vr) {
    int which = blockIdx.z;
    const float* Z = (which == 0) ? qz : (which == 1) ? kz : vz;
    const float* R = (which == 0) ? qr : (which == 1) ? kr : vr;
    float* Cw = g_qkv[which];

    __shared__ unsigned As[128][36];   // [m][k], stride 36
    __shared__ unsigned Bs[32][136];   // [k][n], stride 136

    int t = threadIdx.x;
    int wid = t >> 5, lane = t & 31;
    int L2 = lane >> 2, L0 = lane & 3;
    int wm = wid >> 1, wn = wid & 1;
    int m0 = blockIdx.x * 128, n0 = blockIdx.y * 128;

    float acc[2][8][4] = {};
    float assq[4] = {};    // partial ||x_row||^2 (4 rows/thread)
    float bssq[4] = {};    // partial ||z_col||^2 (4 cols/thread)

    for (int k0 = 0; k0 < DM; k0 += 32) {
        #pragma unroll
        for (int j = 0; j < 4; j++) {       // A: 128x32
            int idx = t + j * 256;
            int m = idx >> 3, kc = (idx & 7) * 4;
            float4 v = *(const float4*)&X[(m0 + m) * DM + k0 + kc];
            assq[j] = fmaf(v.x, v.x, fmaf(v.y, v.y, fmaf(v.z, v.z, fmaf(v.w, v.w, assq[j]))));
            *(uint4*)&As[m][kc] = make_uint4(f2tf32(v.x), f2tf32(v.y), f2tf32(v.z), f2tf32(v.w));
        }
        #pragma unroll
        for (int j = 0; j < 4; j++) {       // B: 32x128
            int idx = t + j * 256;
            int kk = idx >> 5, nn = (idx & 31) * 4;
            float4 v = *(const float4*)&Z[(k0 + kk) * DM + n0 + nn];
            bssq[0] = fmaf(v.x, v.x, bssq[0]); bssq[1] = fmaf(v.y, v.y, bssq[1]);
            bssq[2] = fmaf(v.z, v.z, bssq[2]); bssq[3] = fmaf(v.w, v.w, bssq[3]);
            *(uint4*)&Bs[kk][nn] = make_uint4(f2tf32(v.x), f2tf32(v.y), f2tf32(v.z), f2tf32(v.w));
        }
        __syncthreads();
        #pragma unroll
        for (int k8 = 0; k8 < 4; k8++) {
            int kb = k8 * 8 + L0;
            unsigned a[2][4];
            #pragma unroll
            for (int mt = 0; mt < 2; mt++) {
                int r = wm * 32 + mt * 16 + L2;
                a[mt][0] = As[r][kb];     a[mt][1] = As[r + 8][kb];
                a[mt][2] = As[r][kb + 4]; a[mt][3] = As[r + 8][kb + 4];
            }
            #pragma unroll
            for (int nt = 0; nt < 8; nt++) {
                int c = wn * 64 + nt * 8 + L2;
                unsigned b[2] = { Bs[kb][c], Bs[kb + 4][c] };
                mma8(acc[0][nt], a[0], b);
                mma8(acc[1][nt], a[1], b);
            }
        }
        __syncthreads();
    }

    // ---- reduce fused norms (stage partials through As region) ----
    float* rowp = (float*)As;              // [128][9]
    float* colp = rowp + 1152;             // [32 col4][8 warp] float4
    #pragma unroll
    for (int j = 0; j < 4; j++)
        rowp[(j * 32 + (t >> 3)) * 9 + (t & 7)] = assq[j];
    *(float4*)&colp[(((t & 31) * 8) + (t >> 5)) * 4] = make_float4(bssq[0], bssq[1], bssq[2], bssq[3]);
    __syncthreads();

    float* scA  = (float*)Bs;              // 2*cosh(2r)/zn for 128 cols
    float* szn2 = scA + 128;               // 2*zn
    float* ssh  = szn2 + 128;              // sinh(2r)
    float* scx  = ssh + 128;               // ||x_row||^2 for 128 rows
    if (t < 128) {
        float s = 0.f;
        #pragma unroll
        for (int i = 0; i < 8; i++) s += rowp[t * 9 + i];
        scx[t] = s;
        float zs = 0.f;
        #pragma unroll
        for (int i = 0; i < 8; i++) zs += colp[((t >> 2) * 8 + i) * 4 + (t & 3)];
        float zn = fmaxf(fsqrt_a(zs), 1e-15f);
        float rv = 2.0f * R[n0 + t];
        float e  = fex2_a(rv * 1.44269504f);
        float ie = frcp_a(e);
        scA[t]  = (e + ie) * frcp_a(zn);   // 2*cosh(2r)/zn
        szn2[t] = 2.0f * zn;
        ssh[t]  = 0.5f * (e - ie);
    }
    __syncthreads();

    // ---- fused Poincare epilogue ----
    int head = (n0 >> 6) + wn;
    #pragma unroll
    for (int mt = 0; mt < 2; mt++) {
        #pragma unroll
        for (int hh = 0; hh < 2; hh++) {
            int rloc = wm * 32 + mt * 16 + hh * 8 + L2;
            float cx2 = scx[rloc];
            float invden = frcp_a(fmaxf(1.0f - cx2, 1e-15f));
            float opc = 1.0f + cx2;
            float sq = 0.f;
            #pragma unroll
            for (int nt = 0; nt < 8; nt++) {
                int cl = wn * 64 + nt * 8 + 2 * L0;
                #pragma unroll
                for (int u = 0; u < 2; u++) {
                    float xz  = acc[mt][nt][hh * 2 + u];
                    float arg = fmaf(xz, scA[cl + u], -opc * ssh[cl + u]) * invden;
                    float aa  = fabsf(arg);
                    float A   = aa + fsqrt_a(fmaf(aa, aa, 1.0f));
                    float tE  = fex2_a(szn2[cl + u] * flg2_a(A));
                    float y   = copysignf(0.5f * (tE - frcp_a(tE)), arg);
                    acc[mt][nt][hh * 2 + u] = y;
                    sq = fmaf(y, y, sq);
                }
            }
            sq += __shfl_xor_sync(0xffffffffu, sq, 1);
            sq += __shfl_xor_sync(0xffffffffu, sq, 2);
            float n1  = fmaxf(sqrtf(sq), 1e-15f);
            float s1  = (n1 > MAXN) ? (MAXN / n1) : 1.0f;
            float n1c = n1 * s1;
            float f   = 1.0f / (1.0f + sqrtf(1.0f + n1c * n1c));
            float n2  = fmaxf(n1c * f, 1e-15f);
            float s2v = (n2 > MAXN) ? (MAXN / n2) : 1.0f;
            float hs  = s1 * f * s2v;
            float n3  = n2 * s2v;
            int grow = m0 + rloc;
            if (L0 == 0) g_aux[which][grow * NH + head] = n3 * n3;
            #pragma unroll
            for (int nt = 0; nt < 8; nt++) {
                int cl = wn * 64 + nt * 8 + 2 * L0;
                *(float2*)&Cw[grow * DM + n0 + cl] =
                    make_float2(acc[mt][nt][hh * 2] * hs, acc[mt][nt][hh * 2 + 1] * hs);
            }
        }
    }
}

// ---------------------------------------------------------------------------
// Kernel 2: flash-style hyperbolic attention.
// exp(-arccosh(1+tt)) = 1/((1+tt)+sqrt(tt*(tt+2)))  (cancellation-free)
// Online normalization in ratio space (softmax is scale-invariant).
// ---------------------------------------------------------------------------
#define ATT_SMEM_WORDS (128*68 + 64*68 + 128*68 + 64*72 + 128 + 4*64)
__global__ __launch_bounds__(256, 2)
void attn_kernel(const float* __restrict__ mask, float* __restrict__ out) {
    extern __shared__ unsigned smu[];
    unsigned (*qsm)[68] = (unsigned(*)[68])smu;                 // [i][d]
    unsigned (*ksm)[68] = (unsigned(*)[68])(smu + 128*68);      // [j][d]
    unsigned (*ps )[68] = (unsigned(*)[68])(smu + 192*68);      // [i][j]
    unsigned (*vsm)[72] = (unsigned(*)[72])(smu + 320*68);      // [j][d] gamma*V
    float* q2s  = (float*)(smu + 320*68 + 64*72);               // 128
    float* k2s  = q2s + 128;                                    // 64
    float* iks  = k2s + 64;                                     // 64: 1/(1-k2)
    float* gm1s = iks + 64;                                     // 64: gamma_v-1
    float* emk  = gm1s + 64;                                    // 64: exp(mask)

    int bh = blockIdx.x, qt = blockIdx.y;
    int b = bh >> 4, h = bh & 15;
    int t = threadIdx.x, wid = t >> 5, lane = t & 31;
    int L2 = lane >> 2, L0 = lane & 3;
    int qi0 = qt * 128;

    const float* Q = g_qkv[0];
    const float* K = g_qkv[1];
    const float* V = g_qkv[2];

    #pragma unroll
    for (int j = 0; j < 8; j++) {
        int idx = t + j * 256;
        int row = idx >> 4, c4 = (idx & 15) * 4;
        float4 v = *(const float4*)&Q[(b * SS + qi0 + row) * DM + h * DH + c4];
        *(uint4*)&qsm[row][c4] = make_uint4(f2tf32(v.x), f2tf32(v.y), f2tf32(v.z), f2tf32(v.w));
    }
    if (t < 128) q2s[t] = g_aux[0][(b * SS + qi0 + t) * NH + h];
    __syncthreads();

    int rA = wid * 16 + L2;
    float q2_0 = q2s[rA], q2_1 = q2s[rA + 8];
    float tiq0 = 2.0f * frcp_a(fmaxf(1.0f - q2_0, 1e-15f));
    float tiq1 = 2.0f * frcp_a(fmaxf(1.0f - q2_1, 1e-15f));

    float o[8][4] = {};
    float accd0 = 0.f, accd1 = 0.f;
    float m0r = 0.f, m1r = 0.f;           // running max of ratio weights

    for (int kt = 0; kt < SS / 64; kt++) {
        int kj0 = kt * 64;
        #pragma unroll
        for (int j = 0; j < 4; j++) {
            int idx = t + j * 256;
            int row = idx >> 4, c4 = (idx & 15) * 4;
            int gr = b * SS + kj0 + row;
            float4 kv = *(const float4*)&K[gr * DM + h * DH + c4];
            *(uint4*)&ksm[row][c4] = make_uint4(f2tf32(kv.x), f2tf32(kv.y), f2tf32(kv.z), f2tf32(kv.w));
            float v2 = g_aux[2][gr * NH + h];
            float gam = 2.0f * frcp_a(fmaxf(1.0f - v2, 1e-15f));
            float4 vv = *(const float4*)&V[gr * DM + h * DH + c4];
            *(uint4*)&vsm[row][c4] = make_uint4(f2tf32(vv.x * gam), f2tf32(vv.y * gam),
                                                f2tf32(vv.z * gam), f2tf32(vv.w * gam));
        }
        if (t < 64) {
            int gr = b * SS + kj0 + t;
            float k2 = g_aux[1][gr * NH + h];
            k2s[t] = k2;
            iks[t] = frcp_a(fmaxf(1.0f - k2, 1e-15f));
            float v2 = g_aux[2][gr * NH + h];
            gm1s[t] = 2.0f * frcp_a(fmaxf(1.0f - v2, 1e-15f)) - 1.0f;
            emk[t] = __expf(mask[b * SS + kj0 + t]);
        }
        __syncthreads();

        // --- QK^T ---
        float s[8][4] = {};
        #pragma unroll
        for (int k8 = 0; k8 < 8; k8++) {
            int kb = k8 * 8 + L0;
            unsigned a[4] = { qsm[rA][kb], qsm[rA + 8][kb], qsm[rA][kb + 4], qsm[rA + 8][kb + 4] };
            #pragma unroll
            for (int nt = 0; nt < 8; nt++) {
                int c = nt * 8 + L2;
                unsigned bb[2] = { ksm[c][kb], ksm[c][kb + 4] };
                mma8(s[nt], a, bb);
            }
        }

        // --- weight w = exp(mask)/((1+tt)+sqrt(tt*(tt+2))), tt = 2*num/den ---
        float pm0 = 0.f, pm1 = 0.f;
        #pragma unroll
        for (int nt = 0; nt < 8; nt++) {
            int j0 = nt * 8 + 2 * L0;
            float k20 = k2s[j0], k21 = k2s[j0 + 1];
            float ik0 = iks[j0], ik1 = iks[j0 + 1];
            float em0 = emk[j0], em1 = emk[j0 + 1];
            #pragma unroll
            for (int e = 0; e < 4; e++) {
                float q2v = (e < 2) ? q2_0 : q2_1;
                float cc  = ((e < 2) ? tiq0 : tiq1) * ((e & 1) ? ik1 : ik0);
                float k2v = (e & 1) ? k21 : k20;
                float emv = (e & 1) ? em1 : em0;
                float num = fmaxf(fmaf(-2.0f, s[nt][e], q2v + k2v), 1e-15f);
                float tt  = num * cc;
                float sr  = fsqrt_a(tt * (tt + 2.0f));
                s[nt][e]  = __fdividef(emv, (1.0f + tt) + sr);
            }
            pm0 = fmaxf(pm0, fmaxf(s[nt][0], s[nt][1]));
            pm1 = fmaxf(pm1, fmaxf(s[nt][2], s[nt][3]));
        }
        pm0 = fmaxf(pm0, __shfl_xor_sync(0xffffffffu, pm0, 1));
        pm0 = fmaxf(pm0, __shfl_xor_sync(0xffffffffu, pm0, 2));
        pm1 = fmaxf(pm1, __shfl_xor_sync(0xffffffffu, pm1, 1));
        pm1 = fmaxf(pm1, __shfl_xor_sync(0xffffffffu, pm1, 2));
        float mn0 = fmaxf(m0r, pm0), mn1 = fmaxf(m1r, pm1);
        float sc0 = __fdividef(m0r, mn0), sc1 = __fdividef(m1r, mn1);
        float iw0 = frcp_a(mn0), iw1 = frcp_a(mn1);
        m0r = mn0; m1r = mn1;
        accd0 *= sc0; accd1 *= sc1;
        #pragma unroll
        for (int nt = 0; nt < 8; nt++) {
            o[nt][0] *= sc0; o[nt][1] *= sc0;
            o[nt][2] *= sc1; o[nt][3] *= sc1;
        }
        #pragma unroll
        for (int nt = 0; nt < 8; nt++) {
            int j0 = nt * 8 + 2 * L0;
            float p00 = s[nt][0] * iw0, p01 = s[nt][1] * iw0;
            float p10 = s[nt][2] * iw1, p11 = s[nt][3] * iw1;
            float g0 = gm1s[j0], g1 = gm1s[j0 + 1];
            accd0 = fmaf(p00, g0, fmaf(p01, g1, accd0));
            accd1 = fmaf(p10, g0, fmaf(p11, g1, accd1));
            ps[rA][j0]     = f2tf32(p00); ps[rA][j0 + 1]     = f2tf32(p01);
            ps[rA + 8][j0] = f2tf32(p10); ps[rA + 8][j0 + 1] = f2tf32(p11);
        }
        __syncwarp();

        // --- P @ (gamma V) ---
        #pragma unroll
        for (int k8 = 0; k8 < 8; k8++) {
            int kb = k8 * 8 + L0;
            unsigned a[4] = { ps[rA][kb], ps[rA + 8][kb], ps[rA][kb + 4], ps[rA + 8][kb + 4] };
            #pragma unroll
            for (int nt = 0; nt < 8; nt++) {
                int d = nt * 8 + L2;
                unsigned bb[2] = { vsm[kb][d], vsm[kb + 4][d] };
                mma8(o[nt], a, bb);
            }
        }
        __syncthreads();
    }

    // --- finalize: gyromidpoint + project ---
    accd0 += __shfl_xor_sync(0xffffffffu, accd0, 1);
    accd0 += __shfl_xor_sync(0xffffffffu, accd0, 2);
    accd1 += __shfl_xor_sync(0xffffffffu, accd1, 1);
    accd1 += __shfl_xor_sync(0xffffffffu, accd1, 2);
    #pragma unroll
    for (int rh = 0; rh < 2; rh++) {
        float accd = rh ? accd1 : accd0;
        float invd = 1.0f / fmaxf(accd, 1e-10f);
        float tm[8][2];
        float sq = 0.f;
        #pragma unroll
        for (int nt = 0; nt < 8; nt++) {
            tm[nt][0] = o[nt][rh * 2 + 0] * invd;
            tm[nt][1] = o[nt][rh * 2 + 1] * invd;
            sq += tm[nt][0] * tm[nt][0] + tm[nt][1] * tm[nt][1];
        }
        sq += __shfl_xor_sync(0xffffffffu, sq, 1);
        sq += __shfl_xor_sync(0xffffffffu, sq, 2);
        float f = 1.0f / (1.0f + sqrtf(fmaxf(1.0f - sq, 1e-15f)));
        float n = fmaxf(sqrtf(sq) * f, 1e-15f);
        float s2 = (n > MAXN) ? (MAXN / n) : 1.0f;
        float g = f * s2;
        int qrow = qi0 + rA + rh * 8;
        #pragma unroll
        for (int nt = 0; nt < 8; nt++) {
            *(float2*)&out[(b * SS + qrow) * DM + h * DH + nt * 8 + 2 * L0] =
                make_float2(tm[nt][0] * g, tm[nt][1] * g);
        }
    }
}

// ---------------------------------------------------------------------------
extern "C" void kernel_launch(void* const* d_in, const int* in_sizes, int n_in,
                              void* d_out, int out_size) {
    const float* hidden = (const float*)d_in[0];
    const float* amask  = (const float*)d_in[1];
    const float* qz = (const float*)d_in[2];
    const float* qr = (const float*)d_in[3];
    const float* kz = (const float*)d_in[4];
    const float* kr = (const float*)d_in[5];
    const float* vz = (const float*)d_in[6];
    const float* vr = (const float*)d_in[7];
    float* out = (float*)d_out;

    static bool attr_done = false;
    if (!attr_done) {
        cudaFuncSetAttribute(attn_kernel, cudaFuncAttributeMaxDynamicSharedMemorySize,
                             ATT_SMEM_WORDS * 4);
        attr_done = true;
    }

    gemm_proj_kernel<<<dim3(MROWS / 128, DM / 128, 3), 256>>>(hidden, qz, kz, vz, qr, kr, vr);
    attn_kernel<<<dim3(BB * NH, SS / 128), 256, ATT_SMEM_WORDS * 4>>>(amask, out);
}